// round 2
// baseline (speedup 1.0000x reference)
#include <cuda_runtime.h>
#include <cuda_bf16.h>

#define N 8192
#define D 128
#define BI 64
#define BJ 64
#define JCHUNK 1024
#define NJB (N / JCHUNK)        // 8
#define NTILES (JCHUNK / BJ)    // 16
#define MAIN_SMEM ((D * BI + D * BJ) * (int)sizeof(float))  // 64 KB

__device__ float    g_sq[N];
__device__ unsigned g_maxpos[N];   // float bits, all values >= 0 so uint order == float order
__device__ unsigned g_minneg[N];

// ---------------------------------------------------------------------------
// K0: per-row squared norms + init of the max/min accumulators
// ---------------------------------------------------------------------------
__global__ void init_kernel(const float* __restrict__ x) {
    int i = blockIdx.x * blockDim.x + threadIdx.x;
    if (i < N) {
        const float4* row = (const float4*)(x + (size_t)i * D);
        float s = 0.f;
#pragma unroll
        for (int k = 0; k < D / 4; k++) {
            float4 v = row[k];
            s += v.x * v.x + v.y * v.y + v.z * v.z + v.w * v.w;
        }
        g_sq[i] = s;
        g_maxpos[i] = 0u;                        // 0.0f — diag guarantees maxpos >= 0
        g_minneg[i] = __float_as_uint(1e30f);
    }
}

// ---------------------------------------------------------------------------
// K1: tiled Gram matrix with fused hardest-positive / hardest-negative epilogue
// grid: (N/BI, NJB) = (128, 8); block: 256 threads; 64 KB dynamic smem
// thread (tx,ty) owns a 4x4 register tile: rows i0+ty*4.., cols j0+tx*4..
// ---------------------------------------------------------------------------
__global__ void __launch_bounds__(256)
main_kernel(const float* __restrict__ x, const int* __restrict__ lab) {
    extern __shared__ float smem[];
    float* As = smem;            // [D][BI]  (k-major, i contiguous)
    float* Bs = smem + D * BI;   // [D][BJ]  (k-major, j contiguous)

    const int tid = threadIdx.x;
    const int tx = tid & 15;
    const int ty = tid >> 4;
    const int i0 = blockIdx.x * BI;
    const int j0base = blockIdx.y * JCHUNK;

    // --- load A tile transposed (once per block) ---
    {
        const int r  = tid & 63;          // local row
        const int k4 = (tid >> 6) * 4;    // 0,4,8,12
#pragma unroll
        for (int p = 0; p < 8; p++) {
            int k = k4 + p * 16;
            float4 v = *(const float4*)(x + (size_t)(i0 + r) * D + k);
            As[(k + 0) * BI + r] = v.x;
            As[(k + 1) * BI + r] = v.y;
            As[(k + 2) * BI + r] = v.z;
            As[(k + 3) * BI + r] = v.w;
        }
    }

    float sqi[4];
    int   li[4];
#pragma unroll
    for (int r = 0; r < 4; r++) {
        int i = i0 + ty * 4 + r;
        sqi[r] = g_sq[i];
        li[r]  = lab[i];
    }

    float maxpos[4], minneg[4];
#pragma unroll
    for (int r = 0; r < 4; r++) { maxpos[r] = -1e30f; minneg[r] = 1e30f; }

    for (int t = 0; t < NTILES; t++) {
        const int j0 = j0base + t * BJ;

        __syncthreads();   // protect Bs (and As on first iter) before overwrite
        {
            const int r  = tid & 63;
            const int k4 = (tid >> 6) * 4;
#pragma unroll
            for (int p = 0; p < 8; p++) {
                int k = k4 + p * 16;
                float4 v = *(const float4*)(x + (size_t)(j0 + r) * D + k);
                Bs[(k + 0) * BJ + r] = v.x;
                Bs[(k + 1) * BJ + r] = v.y;
                Bs[(k + 2) * BJ + r] = v.z;
                Bs[(k + 3) * BJ + r] = v.w;
            }
        }
        __syncthreads();

        float acc[4][4];
#pragma unroll
        for (int r = 0; r < 4; r++)
#pragma unroll
            for (int c = 0; c < 4; c++) acc[r][c] = 0.f;

#pragma unroll 16
        for (int k = 0; k < D; k++) {
            float4 a = *(const float4*)&As[k * BI + ty * 4];
            float4 b = *(const float4*)&Bs[k * BJ + tx * 4];
            acc[0][0] += a.x * b.x; acc[0][1] += a.x * b.y; acc[0][2] += a.x * b.z; acc[0][3] += a.x * b.w;
            acc[1][0] += a.y * b.x; acc[1][1] += a.y * b.y; acc[1][2] += a.y * b.z; acc[1][3] += a.y * b.w;
            acc[2][0] += a.z * b.x; acc[2][1] += a.z * b.y; acc[2][2] += a.z * b.z; acc[2][3] += a.z * b.w;
            acc[3][0] += a.w * b.x; acc[3][1] += a.w * b.y; acc[3][2] += a.w * b.z; acc[3][3] += a.w * b.w;
        }

        // fused epilogue: distance -> label-masked max/min
#pragma unroll
        for (int c = 0; c < 4; c++) {
            int j = j0 + tx * 4 + c;
            float sqj = g_sq[j];
            int   lj  = lab[j];
#pragma unroll
            for (int r = 0; r < 4; r++) {
                float dist = fmaxf(sqi[r] + sqj - 2.f * acc[r][c], 0.f);
                if (li[r] == lj) maxpos[r] = fmaxf(maxpos[r], dist);
                else             minneg[r] = fminf(minneg[r], dist);
            }
        }
    }

    // reduce across the 16 tx lanes (warp halves: offsets 8,4,2,1 stay in-half)
#pragma unroll
    for (int r = 0; r < 4; r++) {
#pragma unroll
        for (int off = 8; off > 0; off >>= 1) {
            maxpos[r] = fmaxf(maxpos[r], __shfl_xor_sync(0xffffffffu, maxpos[r], off));
            minneg[r] = fminf(minneg[r], __shfl_xor_sync(0xffffffffu, minneg[r], off));
        }
    }
    if (tx == 0) {
#pragma unroll
        for (int r = 0; r < 4; r++) {
            int i = i0 + ty * 4 + r;
            // clamp to 0: true hardest-positive >= dist(i,i) = 0, so 0 is a no-op candidate
            atomicMax(&g_maxpos[i], __float_as_uint(fmaxf(maxpos[r], 0.f)));
            atomicMin(&g_minneg[i], __float_as_uint(minneg[r]));
        }
    }
}

// ---------------------------------------------------------------------------
// K2: loss = sum relu(maxpos - minneg + margin); single block, bitwise-deterministic
// ---------------------------------------------------------------------------
__global__ void final_kernel(float* __restrict__ out) {
    __shared__ float red[256];
    float s = 0.f;
    for (int i = threadIdx.x; i < N; i += 256) {
        float v = __uint_as_float(g_maxpos[i]) - __uint_as_float(g_minneg[i]) + 0.5f;
        s += fmaxf(v, 0.f);
    }
    red[threadIdx.x] = s;
    __syncthreads();
#pragma unroll
    for (int w = 128; w > 0; w >>= 1) {
        if (threadIdx.x < w) red[threadIdx.x] += red[threadIdx.x + w];
        __syncthreads();
    }
    if (threadIdx.x == 0) out[0] = red[0];
}

extern "C" void kernel_launch(void* const* d_in, const int* in_sizes, int n_in,
                              void* d_out, int out_size) {
    const float* x   = (const float*)d_in[0];
    const int*   lab = (const int*)d_in[1];
    float*       out = (float*)d_out;

    cudaFuncSetAttribute(main_kernel, cudaFuncAttributeMaxDynamicSharedMemorySize, MAIN_SMEM);

    init_kernel<<<(N + 255) / 256, 256>>>(x);
    main_kernel<<<dim3(N / BI, NJB), 256, MAIN_SMEM>>>(x, lab);
    final_kernel<<<1, 256>>>(out);
}

// round 4
// speedup vs baseline: 6.5709x; 6.5709x over previous
#include <cuda_runtime.h>
#include <cuda_fp16.h>

#define N 8192
#define D 128
#define BM 128
#define BN 128
#define MARGIN 0.5f

// smem layout (bytes): A tile, B tile (row-major, 16 chunks of 16B per row,
// chunk-XOR swizzled), j-tile meta, cross-warp reduction buffers
#define SM_A    0
#define SM_B    32768
#define SM_META 65536                    // float2[128]
#define SM_RMAX 66560                    // float[128]
#define SM_RMIN 67072                    // float[128]
#define SMEM_TOTAL 67584

__device__ uint4    g_xh4[N * D / 8];    // fp16 copy of inputs, 16B chunks (8 f16)
__device__ float2   g_meta[N];           // (sq_norm, label bits)
__device__ unsigned g_maxpos[N];         // float bits; >=0 so uint order == float order
__device__ unsigned g_minneg[N];

// ---------------------------------------------------------------------------
// K0: fp16 copy + squared norms + meta + accumulator init
// ---------------------------------------------------------------------------
__global__ void init_kernel(const float* __restrict__ x, const int* __restrict__ lab) {
    int i = blockIdx.x * blockDim.x + threadIdx.x;
    if (i >= N) return;
    const float4* row = (const float4*)(x + (size_t)i * D);
    float s = 0.f;
#pragma unroll
    for (int k = 0; k < 16; k++) {
        float4 a = row[2 * k], b = row[2 * k + 1];
        s += a.x * a.x + a.y * a.y + a.z * a.z + a.w * a.w;
        s += b.x * b.x + b.y * b.y + b.z * b.z + b.w * b.w;
        __half2 h0 = __floats2half2_rn(a.x, a.y);
        __half2 h1 = __floats2half2_rn(a.z, a.w);
        __half2 h2 = __floats2half2_rn(b.x, b.y);
        __half2 h3 = __floats2half2_rn(b.z, b.w);
        uint4 o;
        o.x = *(unsigned*)&h0; o.y = *(unsigned*)&h1;
        o.z = *(unsigned*)&h2; o.w = *(unsigned*)&h3;
        g_xh4[i * 16 + k] = o;
    }
    g_meta[i] = make_float2(s, __int_as_float(lab[i]));
    g_maxpos[i] = 0u;
    g_minneg[i] = __float_as_uint(1e30f);
}

static __device__ __forceinline__ void ldm_x4(unsigned& r0, unsigned& r1,
                                              unsigned& r2, unsigned& r3, unsigned a) {
    asm volatile("ldmatrix.sync.aligned.m8n8.x4.shared.b16 {%0,%1,%2,%3}, [%4];"
                 : "=r"(r0), "=r"(r1), "=r"(r2), "=r"(r3) : "r"(a));
}
static __device__ __forceinline__ void mma16816(float* d, const unsigned* a, const unsigned* b) {
    asm volatile(
        "mma.sync.aligned.m16n8k16.row.col.f32.f16.f16.f32 "
        "{%0,%1,%2,%3}, {%4,%5,%6,%7}, {%8,%9}, {%0,%1,%2,%3};"
        : "+f"(d[0]), "+f"(d[1]), "+f"(d[2]), "+f"(d[3])
        : "r"(a[0]), "r"(a[1]), "r"(a[2]), "r"(a[3]), "r"(b[0]), "r"(b[1]));
}

// ---------------------------------------------------------------------------
// K1: mma.sync f16 Gram tile (128x128, K=128) + fused hardest-pos/neg epilogue
// 256 threads = 8 warps (4 in M x 2 in N); warp tile 32(M) x 64(N)
// ---------------------------------------------------------------------------
__global__ void __launch_bounds__(256, 2)
main_kernel() {
    extern __shared__ char smem[];
    unsigned sb;
    asm("{ .reg .u64 t; cvta.to.shared.u64 t, %1; cvt.u32.u64 %0, t; }"
        : "=r"(sb) : "l"(smem));

    const int tid   = threadIdx.x;
    const int lane  = tid & 31;
    const int wid   = tid >> 5;
    const int wm    = wid & 3;          // warp row
    const int wn    = wid >> 2;         // warp col
    const int i0    = blockIdx.x * BM;
    const int j0    = blockIdx.y * BN;

    // --- fill A/B tiles: row-major 16B chunks, chunk c stored at (c ^ (row&7)) ---
#pragma unroll
    for (int t = 0; t < 8; t++) {
        int idx = tid + t * 256;                 // 0..2047
        int row = idx >> 4, c = idx & 15;
        unsigned off = row * 256 + ((c ^ (row & 7)) << 4);
        *(uint4*)(smem + SM_A + off) = g_xh4[((size_t)(i0 + row) << 4) + c];
        *(uint4*)(smem + SM_B + off) = g_xh4[((size_t)(j0 + row) << 4) + c];
    }
    if (tid < 128) ((float2*)(smem + SM_META))[tid] = g_meta[j0 + tid];
    __syncthreads();

    // --- precomputed ldmatrix source addresses (chunk index varies with ks) ---
    // A frag (mt): row = wm*32 + mt*16 + (lane & 15); chunk = 2*ks + (lane >> 4)
    const int aRow0 = wm * 32 + (lane & 15);
    const unsigned aBase0 = sb + SM_A + aRow0 * 256;
    const unsigned aBase1 = aBase0 + 16 * 256;
    const int aSw0 = aRow0 & 7, aSw1 = (aRow0 + 16) & 7;
    const int aCb  = lane >> 4;
    // B frag pair (ntp): row = wn*64 + ntp*16 + (lane&7) + ((lane>>4)<<3); chunk = 2*ks + ((lane>>3)&1)
    const int bRowL = wn * 64 + (lane & 7) + ((lane >> 4) << 3);
    const int bCb   = (lane >> 3) & 1;

    float d[2][8][4];
#pragma unroll
    for (int mt = 0; mt < 2; mt++)
#pragma unroll
        for (int nt = 0; nt < 8; nt++)
#pragma unroll
            for (int r = 0; r < 4; r++) d[mt][nt][r] = 0.f;

#pragma unroll
    for (int ks = 0; ks < 8; ks++) {
        unsigned a[2][4];
        ldm_x4(a[0][0], a[0][1], a[0][2], a[0][3],
               aBase0 + (((2 * ks + aCb) ^ aSw0) << 4));
        ldm_x4(a[1][0], a[1][1], a[1][2], a[1][3],
               aBase1 + (((2 * ks + aCb) ^ aSw1) << 4));
        unsigned b[8][2];
#pragma unroll
        for (int ntp = 0; ntp < 4; ntp++) {
            int row = bRowL + ntp * 16;
            unsigned addr = sb + SM_B + row * 256 + (((2 * ks + bCb) ^ (row & 7)) << 4);
            ldm_x4(b[2 * ntp][0], b[2 * ntp][1], b[2 * ntp + 1][0], b[2 * ntp + 1][1], addr);
        }
#pragma unroll
        for (int mt = 0; mt < 2; mt++)
#pragma unroll
            for (int nt = 0; nt < 8; nt++)
                mma16816(d[mt][nt], a[mt], b[nt]);
    }

    // --- fused epilogue: v = sqj - 2*dot; per-row masked max/min ---
    const float2* metaS = (const float2*)(smem + SM_META);
    int   li[2][2];
#pragma unroll
    for (int mt = 0; mt < 2; mt++)
#pragma unroll
        for (int p = 0; p < 2; p++)
            li[mt][p] = __float_as_int(g_meta[i0 + wm * 32 + mt * 16 + (lane >> 2) + p * 8].y);

    float vmax[2][2], vmin[2][2];
#pragma unroll
    for (int mt = 0; mt < 2; mt++)
#pragma unroll
        for (int p = 0; p < 2; p++) { vmax[mt][p] = -1e30f; vmin[mt][p] = 1e30f; }

#pragma unroll
    for (int nt = 0; nt < 8; nt++) {
        int colb = wn * 64 + nt * 8 + (lane & 3) * 2;
        float2 m0 = metaS[colb], m1 = metaS[colb + 1];
#pragma unroll
        for (int mt = 0; mt < 2; mt++)
#pragma unroll
            for (int r = 0; r < 4; r++) {
                float2 m = (r & 1) ? m1 : m0;
                float v = fmaf(d[mt][nt][r], -2.f, m.x);
                int p = r >> 1;
                if (__float_as_int(m.y) == li[mt][p]) vmax[mt][p] = fmaxf(vmax[mt][p], v);
                else                                   vmin[mt][p] = fminf(vmin[mt][p], v);
            }
    }

    // reduce across the 4 lanes sharing a row (lane&3 group)
#pragma unroll
    for (int mt = 0; mt < 2; mt++)
#pragma unroll
        for (int p = 0; p < 2; p++) {
#pragma unroll
            for (int off = 1; off <= 2; off <<= 1) {
                vmax[mt][p] = fmaxf(vmax[mt][p], __shfl_xor_sync(0xffffffffu, vmax[mt][p], off));
                vmin[mt][p] = fminf(vmin[mt][p], __shfl_xor_sync(0xffffffffu, vmin[mt][p], off));
            }
        }

    // combine the two N-warps via smem, then one atomic pair per row
    float* rmax = (float*)(smem + SM_RMAX);
    float* rmin = (float*)(smem + SM_RMIN);
    if (wn == 1 && (lane & 3) == 0) {
#pragma unroll
        for (int mt = 0; mt < 2; mt++)
#pragma unroll
            for (int p = 0; p < 2; p++) {
                int row = wm * 32 + mt * 16 + (lane >> 2) + p * 8;
                rmax[row] = vmax[mt][p];
                rmin[row] = vmin[mt][p];
            }
    }
    __syncthreads();
    if (wn == 0 && (lane & 3) == 0) {
#pragma unroll
        for (int mt = 0; mt < 2; mt++)
#pragma unroll
            for (int p = 0; p < 2; p++) {
                int row = wm * 32 + mt * 16 + (lane >> 2) + p * 8;
                float mx = fmaxf(vmax[mt][p], rmax[row]);
                float mn = fminf(vmin[mt][p], rmin[row]);
                float sqi = g_meta[i0 + row].x;
                float dp = fmaxf(sqi + mx, 0.f);   // -1e30 sentinel -> 0 (no-op)
                float dn = fmaxf(sqi + mn, 0.f);   // +1e30 sentinel stays huge (no-op)
                atomicMax(&g_maxpos[i0 + row], __float_as_uint(dp));
                atomicMin(&g_minneg[i0 + row], __float_as_uint(dn));
            }
    }
}

// ---------------------------------------------------------------------------
// K2: loss = sum relu(maxpos - minneg + margin); deterministic single block
// ---------------------------------------------------------------------------
__global__ void final_kernel(float* __restrict__ out) {
    __shared__ float red[256];
    float s = 0.f;
    for (int i = threadIdx.x; i < N; i += 256) {
        float v = __uint_as_float(g_maxpos[i]) - __uint_as_float(g_minneg[i]) + MARGIN;
        s += fmaxf(v, 0.f);
    }
    red[threadIdx.x] = s;
    __syncthreads();
#pragma unroll
    for (int w = 128; w > 0; w >>= 1) {
        if (threadIdx.x < w) red[threadIdx.x] += red[threadIdx.x + w];
        __syncthreads();
    }
    if (threadIdx.x == 0) out[0] = red[0];
}

extern "C" void kernel_launch(void* const* d_in, const int* in_sizes, int n_in,
                              void* d_out, int out_size) {
    const float* x   = (const float*)d_in[0];
    const int*   lab = (const int*)d_in[1];
    float*       out = (float*)d_out;

    cudaFuncSetAttribute(main_kernel, cudaFuncAttributeMaxDynamicSharedMemorySize, SMEM_TOTAL);

    init_kernel<<<(N + 255) / 256, 256>>>(x, lab);
    main_kernel<<<dim3(N / BM, N / BN), 256, SMEM_TOTAL>>>();
    final_kernel<<<1, 256>>>(out);
}

// round 5
// speedup vs baseline: 9.2942x; 1.4145x over previous
#include <cuda_runtime.h>
#include <cuda_fp16.h>

#define N 8192
#define D 128
#define BM 128
#define BN 128
#define NB (N / BM)             // 64 blocks per dim
#define NTILES (NB * (NB + 1) / 2)   // 2080 upper-triangular tiles
#define MARGIN 0.5f

// smem layout (bytes)
#define SM_A     0
#define SM_B     32768
#define SM_METAI 65536                 // float2[128] for i-rows
#define SM_METAJ 66560                 // float2[128] for j-rows
#define SMEM_TOTAL 67584
// reduction buffers overlay SM_A after the mainloop:
#define SM_RMAX  0                     // float[2][128]
#define SM_RMIN  1024
#define SM_CMAX  2048                  // float[4][128]
#define SM_CMIN  4096

__device__ uint4    g_xh4[N * D / 8];  // fp16 copy of inputs, 16B chunks (8 f16)
__device__ float2   g_meta[N];         // (sq_norm, label bits)
__device__ unsigned g_maxpos[N];       // float bits; >=0 so uint order == float order
__device__ unsigned g_minneg[N];

// ---------------------------------------------------------------------------
// K0: fp16 copy + squared norms (8 threads/row) + init
// ---------------------------------------------------------------------------
__global__ void init_kernel(const float* __restrict__ x, const int* __restrict__ lab) {
    int t = blockIdx.x * blockDim.x + threadIdx.x;   // 0 .. 65535
    int i = t >> 3;
    int l8 = t & 7;
    const float4* row = (const float4*)(x + (size_t)i * D);
    float s = 0.f;
#pragma unroll
    for (int c = 0; c < 4; c++) {
        float4 a = row[l8 * 4 + c];
        s += a.x * a.x + a.y * a.y + a.z * a.z + a.w * a.w;
        // pair with the neighbor float4 handled by same thread? no: pack 8 f16 from two float4s
        // -> handle packing per single float4 into half of a uint4 chunk instead:
    }
    // convert: each thread owns 2 consecutive 16B-f16 chunks = 16 floats = 4 float4s
#pragma unroll
    for (int c = 0; c < 2; c++) {
        float4 a = row[l8 * 4 + 2 * c];
        float4 b = row[l8 * 4 + 2 * c + 1];
        __half2 h0 = __floats2half2_rn(a.x, a.y);
        __half2 h1 = __floats2half2_rn(a.z, a.w);
        __half2 h2 = __floats2half2_rn(b.x, b.y);
        __half2 h3 = __floats2half2_rn(b.z, b.w);
        uint4 o;
        o.x = *(unsigned*)&h0; o.y = *(unsigned*)&h1;
        o.z = *(unsigned*)&h2; o.w = *(unsigned*)&h3;
        g_xh4[(size_t)i * 16 + l8 * 2 + c] = o;
    }
#pragma unroll
    for (int off = 1; off <= 4; off <<= 1)
        s += __shfl_xor_sync(0xffffffffu, s, off);
    if (l8 == 0) {
        g_meta[i] = make_float2(s, __int_as_float(lab[i]));
        g_maxpos[i] = 0u;
        g_minneg[i] = __float_as_uint(1e30f);
    }
}

static __device__ __forceinline__ void ldm_x4(unsigned& r0, unsigned& r1,
                                              unsigned& r2, unsigned& r3, unsigned a) {
    asm volatile("ldmatrix.sync.aligned.m8n8.x4.shared.b16 {%0,%1,%2,%3}, [%4];"
                 : "=r"(r0), "=r"(r1), "=r"(r2), "=r"(r3) : "r"(a));
}
static __device__ __forceinline__ void mma16816(float* d, const unsigned* a, const unsigned* b) {
    asm volatile(
        "mma.sync.aligned.m16n8k16.row.col.f32.f16.f16.f32 "
        "{%0,%1,%2,%3}, {%4,%5,%6,%7}, {%8,%9}, {%0,%1,%2,%3};"
        : "+f"(d[0]), "+f"(d[1]), "+f"(d[2]), "+f"(d[3])
        : "r"(a[0]), "r"(a[1]), "r"(a[2]), "r"(a[3]), "r"(b[0]), "r"(b[1]));
}

// ---------------------------------------------------------------------------
// K1: upper-triangular Gram tiles; each tile feeds BOTH row-side (i) and
// column-side (j) hardest-pos/neg reductions. max/min idempotent -> diagonal
// tiles need no special casing.
// 256 threads = 8 warps (4 in M x 2 in N); warp tile 32(M) x 64(N)
// ---------------------------------------------------------------------------
__global__ void __launch_bounds__(256, 2)
main_kernel() {
    extern __shared__ char smem[];
    unsigned sb;
    asm("{ .reg .u64 t; cvta.to.shared.u64 t, %1; cvt.u32.u64 %0, t; }"
        : "=r"(sb) : "l"(smem));

    const int tid  = threadIdx.x;
    const int lane = tid & 31;
    const int wid  = tid >> 5;
    const int wm   = wid & 3;
    const int wn   = wid >> 2;

    // triangular tile index -> (bi, bj), bj >= bi ; off(i) = i*NB - i*(i-1)/2
    int k = blockIdx.x;
    int bi = (int)((2.0 * NB + 1.0 - sqrt((2.0 * NB + 1.0) * (2.0 * NB + 1.0) - 8.0 * k)) * 0.5);
    while ((bi + 1) * NB - ((bi + 1) * bi) / 2 <= k) bi++;
    while (bi * NB - (bi * (bi - 1)) / 2 > k) bi--;
    const int bj = bi + (k - (bi * NB - (bi * (bi - 1)) / 2));
    const int i0 = bi * BM;
    const int j0 = bj * BN;

    // --- fill tiles: row-major 16B chunks, chunk c stored at (c ^ (row&7)) ---
#pragma unroll
    for (int t = 0; t < 8; t++) {
        int idx = tid + t * 256;
        int row = idx >> 4, c = idx & 15;
        unsigned off = row * 256 + ((c ^ (row & 7)) << 4);
        *(uint4*)(smem + SM_A + off) = g_xh4[((size_t)(i0 + row) << 4) + c];
        *(uint4*)(smem + SM_B + off) = g_xh4[((size_t)(j0 + row) << 4) + c];
    }
    if (tid < 128) ((float2*)(smem + SM_METAI))[tid] = g_meta[i0 + tid];
    else           ((float2*)(smem + SM_METAJ))[tid - 128] = g_meta[j0 + tid - 128];
    __syncthreads();

    const int aRow0 = wm * 32 + (lane & 15);
    const unsigned aBase0 = sb + SM_A + aRow0 * 256;
    const unsigned aBase1 = aBase0 + 16 * 256;
    const int aSw0 = aRow0 & 7, aSw1 = (aRow0 + 16) & 7;
    const int aCb  = lane >> 4;
    const int bRowL = wn * 64 + (lane & 7) + ((lane >> 4) << 3);
    const int bCb   = (lane >> 3) & 1;

    float d[2][8][4];
#pragma unroll
    for (int mt = 0; mt < 2; mt++)
#pragma unroll
        for (int nt = 0; nt < 8; nt++)
#pragma unroll
            for (int r = 0; r < 4; r++) d[mt][nt][r] = 0.f;

#pragma unroll
    for (int ks = 0; ks < 8; ks++) {
        unsigned a[2][4];
        ldm_x4(a[0][0], a[0][1], a[0][2], a[0][3],
               aBase0 + (((2 * ks + aCb) ^ aSw0) << 4));
        ldm_x4(a[1][0], a[1][1], a[1][2], a[1][3],
               aBase1 + (((2 * ks + aCb) ^ aSw1) << 4));
        unsigned b[8][2];
#pragma unroll
        for (int ntp = 0; ntp < 4; ntp++) {
            int row = bRowL + ntp * 16;
            unsigned addr = sb + SM_B + row * 256 + (((2 * ks + bCb) ^ (row & 7)) << 4);
            ldm_x4(b[2 * ntp][0], b[2 * ntp][1], b[2 * ntp + 1][0], b[2 * ntp + 1][1], addr);
        }
#pragma unroll
        for (int mt = 0; mt < 2; mt++)
#pragma unroll
            for (int nt = 0; nt < 8; nt++)
                mma16816(d[mt][nt], a[mt], b[nt]);
    }

    // --- epilogue: per-element dot -> row-side v = sqj - 2dot, col-side u = sqi - 2dot
    const float2* metaI = (const float2*)(smem + SM_METAI);
    const float2* metaJ = (const float2*)(smem + SM_METAJ);
    float sqi[2][2];
    int   li[2][2];
#pragma unroll
    for (int mt = 0; mt < 2; mt++)
#pragma unroll
        for (int p = 0; p < 2; p++) {
            float2 m = metaI[wm * 32 + mt * 16 + (lane >> 2) + p * 8];
            sqi[mt][p] = m.x;
            li[mt][p]  = __float_as_int(m.y);
        }

    float vmax[2][2], vmin[2][2];
#pragma unroll
    for (int mt = 0; mt < 2; mt++)
#pragma unroll
        for (int p = 0; p < 2; p++) { vmax[mt][p] = -1e30f; vmin[mt][p] = 1e30f; }

    float* cmaxS = (float*)(smem + SM_CMAX);
    float* cminS = (float*)(smem + SM_CMIN);
    float* rmaxS = (float*)(smem + SM_RMAX);
    float* rminS = (float*)(smem + SM_RMIN);
    __syncthreads();   // tiles fully consumed (regs); safe to overlay SM_A

#pragma unroll
    for (int nt = 0; nt < 8; nt++) {
        int colb = wn * 64 + nt * 8 + (lane & 3) * 2;
        float2 m0 = metaJ[colb], m1 = metaJ[colb + 1];
        float cmx[2] = {-1e30f, -1e30f}, cmn[2] = {1e30f, 1e30f};
#pragma unroll
        for (int mt = 0; mt < 2; mt++)
#pragma unroll
            for (int r = 0; r < 4; r++) {
                int q = r & 1, p = r >> 1;
                float2 m = q ? m1 : m0;
                float dot = d[mt][nt][r];
                float v = fmaf(dot, -2.f, m.x);           // row-side (sqj)
                float u = fmaf(dot, -2.f, sqi[mt][p]);    // col-side (sqi)
                if (__float_as_int(m.y) == li[mt][p]) {
                    vmax[mt][p] = fmaxf(vmax[mt][p], v);
                    cmx[q] = fmaxf(cmx[q], u);
                } else {
                    vmin[mt][p] = fminf(vmin[mt][p], v);
                    cmn[q] = fminf(cmn[q], u);
                }
            }
        // column reduce over the 8 row-lanes (lane>>2): offsets 4,8,16
#pragma unroll
        for (int q = 0; q < 2; q++) {
#pragma unroll
            for (int off = 4; off <= 16; off <<= 1) {
                cmx[q] = fmaxf(cmx[q], __shfl_xor_sync(0xffffffffu, cmx[q], off));
                cmn[q] = fminf(cmn[q], __shfl_xor_sync(0xffffffffu, cmn[q], off));
            }
        }
        if ((lane >> 2) == 0) {
#pragma unroll
            for (int q = 0; q < 2; q++) {
                cmaxS[wm * 128 + colb + q] = cmx[q];
                cminS[wm * 128 + colb + q] = cmn[q];
            }
        }
    }

    // row reduce over the 4 col-lanes (lane&3): offsets 1,2
#pragma unroll
    for (int mt = 0; mt < 2; mt++)
#pragma unroll
        for (int p = 0; p < 2; p++) {
#pragma unroll
            for (int off = 1; off <= 2; off <<= 1) {
                vmax[mt][p] = fmaxf(vmax[mt][p], __shfl_xor_sync(0xffffffffu, vmax[mt][p], off));
                vmin[mt][p] = fminf(vmin[mt][p], __shfl_xor_sync(0xffffffffu, vmin[mt][p], off));
            }
        }
    if ((lane & 3) == 0) {
#pragma unroll
        for (int mt = 0; mt < 2; mt++)
#pragma unroll
            for (int p = 0; p < 2; p++) {
                int row = wm * 32 + mt * 16 + (lane >> 2) + p * 8;
                rmaxS[wn * 128 + row] = vmax[mt][p];
                rminS[wn * 128 + row] = vmin[mt][p];
            }
    }
    __syncthreads();

    // final combine: threads 0-127 -> rows (i-side), 128-255 -> cols (j-side)
    if (tid < 128) {
        float mx = fmaxf(rmaxS[tid], rmaxS[128 + tid]);
        float mn = fminf(rminS[tid], rminS[128 + tid]);
        float s = metaI[tid].x;
        atomicMax(&g_maxpos[i0 + tid], __float_as_uint(fmaxf(s + mx, 0.f)));
        atomicMin(&g_minneg[i0 + tid], __float_as_uint(fmaxf(s + mn, 0.f)));
    } else {
        int c = tid - 128;
        float mx = fmaxf(fmaxf(cmaxS[c], cmaxS[128 + c]),
                         fmaxf(cmaxS[256 + c], cmaxS[384 + c]));
        float mn = fminf(fminf(cminS[c], cminS[128 + c]),
                         fminf(cminS[256 + c], cminS[384 + c]));
        float s = metaJ[c].x;
        atomicMax(&g_maxpos[j0 + c], __float_as_uint(fmaxf(s + mx, 0.f)));
        atomicMin(&g_minneg[j0 + c], __float_as_uint(fmaxf(s + mn, 0.f)));
    }
}

// ---------------------------------------------------------------------------
// K2: loss = sum relu(maxpos - minneg + margin); deterministic single block
// ---------------------------------------------------------------------------
__global__ void final_kernel(float* __restrict__ out) {
    __shared__ float red[256];
    float s = 0.f;
    for (int i = threadIdx.x; i < N; i += 256) {
        float v = __uint_as_float(g_maxpos[i]) - __uint_as_float(g_minneg[i]) + MARGIN;
        s += fmaxf(v, 0.f);
    }
    red[threadIdx.x] = s;
    __syncthreads();
#pragma unroll
    for (int w = 128; w > 0; w >>= 1) {
        if (threadIdx.x < w) red[threadIdx.x] += red[threadIdx.x + w];
        __syncthreads();
    }
    if (threadIdx.x == 0) out[0] = red[0];
}

extern "C" void kernel_launch(void* const* d_in, const int* in_sizes, int n_in,
                              void* d_out, int out_size) {
    const float* x   = (const float*)d_in[0];
    const int*   lab = (const int*)d_in[1];
    float*       out = (float*)d_out;

    cudaFuncSetAttribute(main_kernel, cudaFuncAttributeMaxDynamicSharedMemorySize, SMEM_TOTAL);

    init_kernel<<<N * 8 / 256, 256>>>(x, lab);
    main_kernel<<<NTILES, 256, SMEM_TOTAL>>>();
    final_kernel<<<1, 256>>>(out);
}

// round 6
// speedup vs baseline: 10.3735x; 1.1161x over previous
#include <cuda_runtime.h>
#include <cuda_fp16.h>

#define N 8192
#define D 128
#define BM 128
#define BN 128
#define NB 64
#define SJ 4
#define NCTA 544            // sum_{k=1..64} ceil(k/4)
#define MARGIN 0.5f

// smem offsets (bytes)
#define SM_A      0         // 32 KB, strip-resident A tile
#define SM_B0     32768     // 32 KB
#define SM_B1     65536     // 32 KB
#define SM_METAI  98304     // float2[128]
#define SM_METAJ0 99328     // float2[128]
#define SM_METAJ1 100352    // float2[128]
#define SM_RMAX   101376    // float[2][128]
#define SM_RMIN   102400
#define SM_CMAX   103424    // float[4][128]
#define SM_CMIN   105472
#define SMEM_TOTAL 107520   // 105 KB -> 2 CTAs/SM

__device__ uint4    g_xh4[N * D / 8];  // fp16 inputs, 16B chunks
__device__ float2   g_meta[N];         // (sq_norm, label bits)
__device__ unsigned g_maxpos[N];       // float bits; >=0 so uint order == float order
__device__ unsigned g_minneg[N];

// ---------------------------------------------------------------------------
// K0: fp16 copy + squared norms; 16 threads per row
// ---------------------------------------------------------------------------
__global__ void init_kernel(const float* __restrict__ x, const int* __restrict__ lab) {
    int t = blockIdx.x * blockDim.x + threadIdx.x;   // 0 .. N*16-1
    int i = t >> 4, c = t & 15;
    const float4* row = (const float4*)(x + (size_t)i * D);
    float4 a = row[2 * c], b = row[2 * c + 1];
    float s = a.x * a.x + a.y * a.y + a.z * a.z + a.w * a.w
            + b.x * b.x + b.y * b.y + b.z * b.z + b.w * b.w;
    __half2 h0 = __floats2half2_rn(a.x, a.y);
    __half2 h1 = __floats2half2_rn(a.z, a.w);
    __half2 h2 = __floats2half2_rn(b.x, b.y);
    __half2 h3 = __floats2half2_rn(b.z, b.w);
    uint4 o;
    o.x = *(unsigned*)&h0; o.y = *(unsigned*)&h1;
    o.z = *(unsigned*)&h2; o.w = *(unsigned*)&h3;
    g_xh4[(size_t)i * 16 + c] = o;
#pragma unroll
    for (int off = 1; off <= 8; off <<= 1)
        s += __shfl_xor_sync(0xffffffffu, s, off);
    if (c == 0) {
        g_meta[i] = make_float2(s, __int_as_float(lab[i]));
        g_maxpos[i] = 0u;
        g_minneg[i] = __float_as_uint(1e30f);
    }
}

static __device__ __forceinline__ void ldm_x4(unsigned& r0, unsigned& r1,
                                              unsigned& r2, unsigned& r3, unsigned a) {
    asm volatile("ldmatrix.sync.aligned.m8n8.x4.shared.b16 {%0,%1,%2,%3}, [%4];"
                 : "=r"(r0), "=r"(r1), "=r"(r2), "=r"(r3) : "r"(a));
}
static __device__ __forceinline__ void mma16816(float* d, const unsigned* a, const unsigned* b) {
    asm volatile(
        "mma.sync.aligned.m16n8k16.row.col.f32.f16.f16.f32 "
        "{%0,%1,%2,%3}, {%4,%5,%6,%7}, {%8,%9}, {%0,%1,%2,%3};"
        : "+f"(d[0]), "+f"(d[1]), "+f"(d[2]), "+f"(d[3])
        : "r"(a[0]), "r"(a[1]), "r"(a[2]), "r"(a[3]), "r"(b[0]), "r"(b[1]));
}
static __device__ __forceinline__ void cpa16(unsigned dst, const void* src) {
    asm volatile("cp.async.cg.shared.global [%0], [%1], 16;" :: "r"(dst), "l"(src) : "memory");
}
static __device__ __forceinline__ void cpa8(unsigned dst, const void* src) {
    asm volatile("cp.async.ca.shared.global [%0], [%1], 8;" :: "r"(dst), "l"(src) : "memory");
}

// ---------------------------------------------------------------------------
// K1: strip of up to SJ upper-triangular 128x128 Gram tiles per CTA.
// A tile loaded once; B tiles double-buffered via cp.async, prefetched under
// the previous tile's MMA. Each tile feeds row-side (accumulated in regs
// across the strip) and column-side (per-tile) hardest-pos/neg reductions.
// 256 threads = 8 warps (4 in M x 2 in N); warp tile 32(M) x 64(N).
// ---------------------------------------------------------------------------
__global__ void __launch_bounds__(256, 2)
main_kernel() {
    extern __shared__ char smem[];
    unsigned sb;
    asm("{ .reg .u64 t; cvta.to.shared.u64 t, %1; cvt.u32.u64 %0, t; }"
        : "=r"(sb) : "l"(smem));

    const int tid  = threadIdx.x;
    const int lane = tid & 31;
    const int wid  = tid >> 5;
    const int wm   = wid & 3;
    const int wn   = wid >> 2;

    // block -> (bi, strip)
    int rem = blockIdx.x, bi = 0;
    while (rem >= ((NB - bi + SJ - 1) >> 2)) { rem -= (NB - bi + SJ - 1) >> 2; bi++; }
    const int bj0   = bi + rem * SJ;
    const int ntile = min(SJ, NB - bj0);
    const int i0    = bi * BM;

    // --- prologue: A tile + metaI + B0 + metaJ0, one cp.async group ---
#pragma unroll
    for (int t = 0; t < 8; t++) {
        int idx = tid + t * 256;
        int row = idx >> 4, c = idx & 15;
        cpa16(sb + SM_A + row * 256 + ((c ^ (row & 7)) << 4),
              &g_xh4[((size_t)(i0 + row) << 4) + c]);
    }
    {
        int j0 = bj0 * BN;
#pragma unroll
        for (int t = 0; t < 8; t++) {
            int idx = tid + t * 256;
            int row = idx >> 4, c = idx & 15;
            cpa16(sb + SM_B0 + row * 256 + ((c ^ (row & 7)) << 4),
                  &g_xh4[((size_t)(j0 + row) << 4) + c]);
        }
        if (tid < 128) {
            cpa8(sb + SM_METAI + tid * 8, &g_meta[i0 + tid]);
            cpa8(sb + SM_METAJ0 + tid * 8, &g_meta[j0 + tid]);
        }
    }
    asm volatile("cp.async.commit_group;" ::: "memory");

    // ldmatrix addressing constants
    const int aRow0 = wm * 32 + (lane & 15);
    const unsigned aBase0 = sb + SM_A + aRow0 * 256;
    const unsigned aBase1 = aBase0 + 16 * 256;
    const int aSw0 = aRow0 & 7, aSw1 = (aRow0 + 16) & 7;
    const int aCb  = lane >> 4;
    const int bRowL = wn * 64 + (lane & 7) + ((lane >> 4) << 3);
    const int bCb   = (lane >> 3) & 1;

    float sqi[2][2];
    int   li[2][2];
    float vmax[2][2], vmin[2][2];
#pragma unroll
    for (int mt = 0; mt < 2; mt++)
#pragma unroll
        for (int p = 0; p < 2; p++) { vmax[mt][p] = -1e30f; vmin[mt][p] = 1e30f; }

    float* cmaxS = (float*)(smem + SM_CMAX);
    float* cminS = (float*)(smem + SM_CMIN);

    for (int t = 0; t < ntile; t++) {
        asm volatile("cp.async.wait_group 0;" ::: "memory");
        __syncthreads();   // B(t) visible to all; all threads done with buf[(t+1)&1]

        if (t == 0) {
            const float2* metaI = (const float2*)(smem + SM_METAI);
#pragma unroll
            for (int mt = 0; mt < 2; mt++)
#pragma unroll
                for (int p = 0; p < 2; p++) {
                    float2 m = metaI[wm * 32 + mt * 16 + (lane >> 2) + p * 8];
                    sqi[mt][p] = m.x;
                    li[mt][p]  = __float_as_int(m.y);
                }
        }

        // prefetch B(t+1) into the other buffer (overlaps this tile's MMA)
        if (t + 1 < ntile) {
            int jn = (bj0 + t + 1) * BN;
            unsigned bdst = sb + (((t + 1) & 1) ? SM_B1 : SM_B0);
#pragma unroll
            for (int u = 0; u < 8; u++) {
                int idx = tid + u * 256;
                int row = idx >> 4, c = idx & 15;
                cpa16(bdst + row * 256 + ((c ^ (row & 7)) << 4),
                      &g_xh4[((size_t)(jn + row) << 4) + c]);
            }
            if (tid < 128)
                cpa8(sb + (((t + 1) & 1) ? SM_METAJ1 : SM_METAJ0) + tid * 8, &g_meta[jn + tid]);
            asm volatile("cp.async.commit_group;" ::: "memory");
        }

        const unsigned bB = sb + ((t & 1) ? SM_B1 : SM_B0);
        const float2* metaJ = (const float2*)(smem + ((t & 1) ? SM_METAJ1 : SM_METAJ0));
        const int j0t = (bj0 + t) * BN;

        // --- mainloop ---
        float d[2][8][4];
#pragma unroll
        for (int mt = 0; mt < 2; mt++)
#pragma unroll
            for (int nt = 0; nt < 8; nt++)
#pragma unroll
                for (int r = 0; r < 4; r++) d[mt][nt][r] = 0.f;

#pragma unroll
        for (int ks = 0; ks < 8; ks++) {
            unsigned a[2][4];
            ldm_x4(a[0][0], a[0][1], a[0][2], a[0][3],
                   aBase0 + (((2 * ks + aCb) ^ aSw0) << 4));
            ldm_x4(a[1][0], a[1][1], a[1][2], a[1][3],
                   aBase1 + (((2 * ks + aCb) ^ aSw1) << 4));
            unsigned b[8][2];
#pragma unroll
            for (int ntp = 0; ntp < 4; ntp++) {
                int row = bRowL + ntp * 16;
                unsigned addr = bB + row * 256 + (((2 * ks + bCb) ^ (row & 7)) << 4);
                ldm_x4(b[2 * ntp][0], b[2 * ntp][1], b[2 * ntp + 1][0], b[2 * ntp + 1][1], addr);
            }
#pragma unroll
            for (int mt = 0; mt < 2; mt++)
#pragma unroll
                for (int nt = 0; nt < 8; nt++)
                    mma16816(d[mt][nt], a[mt], b[nt]);
        }

        // --- epilogue: row-side accumulates in regs, col-side via smem ---
#pragma unroll
        for (int nt = 0; nt < 8; nt++) {
            int colb = wn * 64 + nt * 8 + (lane & 3) * 2;
            float2 m0 = metaJ[colb], m1 = metaJ[colb + 1];
            float cmx[2] = {-1e30f, -1e30f}, cmn[2] = {1e30f, 1e30f};
#pragma unroll
            for (int mt = 0; mt < 2; mt++)
#pragma unroll
                for (int r = 0; r < 4; r++) {
                    int q = r & 1, p = r >> 1;
                    float2 m = q ? m1 : m0;
                    float dot = d[mt][nt][r];
                    float v = fmaf(dot, -2.f, m.x);          // row-side (sqj)
                    float u = fmaf(dot, -2.f, sqi[mt][p]);   // col-side (sqi)
                    if (__float_as_int(m.y) == li[mt][p]) {
                        vmax[mt][p] = fmaxf(vmax[mt][p], v);
                        cmx[q] = fmaxf(cmx[q], u);
                    } else {
                        vmin[mt][p] = fminf(vmin[mt][p], v);
                        cmn[q] = fminf(cmn[q], u);
                    }
                }
#pragma unroll
            for (int q = 0; q < 2; q++) {
#pragma unroll
                for (int off = 4; off <= 16; off <<= 1) {
                    cmx[q] = fmaxf(cmx[q], __shfl_xor_sync(0xffffffffu, cmx[q], off));
                    cmn[q] = fminf(cmn[q], __shfl_xor_sync(0xffffffffu, cmn[q], off));
                }
            }
            if ((lane >> 2) == 0) {
#pragma unroll
                for (int q = 0; q < 2; q++) {
                    cmaxS[wm * 128 + colb + q] = cmx[q];
                    cminS[wm * 128 + colb + q] = cmn[q];
                }
            }
        }
        __syncthreads();
        if (tid < 128) {
            float mx = fmaxf(fmaxf(cmaxS[tid], cmaxS[128 + tid]),
                             fmaxf(cmaxS[256 + tid], cmaxS[384 + tid]));
            float mn = fminf(fminf(cminS[tid], cminS[128 + tid]),
                             fminf(cminS[256 + tid], cminS[384 + tid]));
            float s = metaJ[tid].x;
            atomicMax(&g_maxpos[j0t + tid], __float_as_uint(fmaxf(s + mx, 0.f)));
            atomicMin(&g_minneg[j0t + tid], __float_as_uint(fmaxf(s + mn, 0.f)));
        }
        // next iteration's top __syncthreads protects cmaxS reuse
    }

    // --- row-side final: reduce 4 col-lanes, combine 2 N-warps, atomics ---
    float* rmaxS = (float*)(smem + SM_RMAX);
    float* rminS = (float*)(smem + SM_RMIN);
#pragma unroll
    for (int mt = 0; mt < 2; mt++)
#pragma unroll
        for (int p = 0; p < 2; p++) {
#pragma unroll
            for (int off = 1; off <= 2; off <<= 1) {
                vmax[mt][p] = fmaxf(vmax[mt][p], __shfl_xor_sync(0xffffffffu, vmax[mt][p], off));
                vmin[mt][p] = fminf(vmin[mt][p], __shfl_xor_sync(0xffffffffu, vmin[mt][p], off));
            }
        }
    __syncthreads();
    if ((lane & 3) == 0) {
#pragma unroll
        for (int mt = 0; mt < 2; mt++)
#pragma unroll
            for (int p = 0; p < 2; p++) {
                int row = wm * 32 + mt * 16 + (lane >> 2) + p * 8;
                rmaxS[wn * 128 + row] = vmax[mt][p];
                rminS[wn * 128 + row] = vmin[mt][p];
            }
    }
    __syncthreads();
    if (tid < 128) {
        float mx = fmaxf(rmaxS[tid], rmaxS[128 + tid]);
        float mn = fminf(rminS[tid], rminS[128 + tid]);
        float s = ((const float2*)(smem + SM_METAI))[tid].x;
        atomicMax(&g_maxpos[i0 + tid], __float_as_uint(fmaxf(s + mx, 0.f)));
        atomicMin(&g_minneg[i0 + tid], __float_as_uint(fmaxf(s + mn, 0.f)));
    }
}

// ---------------------------------------------------------------------------
// K2: loss = sum relu(maxpos - minneg + margin); deterministic single block
// ---------------------------------------------------------------------------
__global__ void final_kernel(float* __restrict__ out) {
    __shared__ float red[1024];
    float s = 0.f;
    for (int i = threadIdx.x; i < N; i += 1024) {
        float v = __uint_as_float(g_maxpos[i]) - __uint_as_float(g_minneg[i]) + MARGIN;
        s += fmaxf(v, 0.f);
    }
    red[threadIdx.x] = s;
    __syncthreads();
#pragma unroll
    for (int w = 512; w > 0; w >>= 1) {
        if (threadIdx.x < w) red[threadIdx.x] += red[threadIdx.x + w];
        __syncthreads();
    }
    if (threadIdx.x == 0) out[0] = red[0];
}

extern "C" void kernel_launch(void* const* d_in, const int* in_sizes, int n_in,
                              void* d_out, int out_size) {
    const float* x   = (const float*)d_in[0];
    const int*   lab = (const int*)d_in[1];
    float*       out = (float*)d_out;

    cudaFuncSetAttribute(main_kernel, cudaFuncAttributeMaxDynamicSharedMemorySize, SMEM_TOTAL);

    init_kernel<<<N * 16 / 256, 256>>>(x, lab);
    main_kernel<<<NCTA, 256, SMEM_TOTAL>>>();
    final_kernel<<<1, 1024>>>(out);
}